// round 1
// baseline (speedup 1.0000x reference)
#include <cuda_runtime.h>
#include <math.h>

// Problem constants
#define NN_ 50000
#define EE_ 600000
#define HH_ 128
#define FF_ 256
#define QQ_ 64

// ---------------- scratch (device globals; no dynamic allocation) ----------
__device__ float g_h0 [NN_ * HH_];
__device__ float g_h1 [NN_ * HH_];
__device__ float g_hA [NN_ * HH_];
__device__ float g_h2 [NN_ * HH_];
__device__ float g_agg[NN_ * HH_];
__device__ float g_hs0[NN_ * HH_];
__device__ float g_hs1[NN_ * HH_];
__device__ float g_t0 [NN_ * QQ_];
__device__ float g_t1 [NN_ * QQ_];

__device__ int   g_cnt_in [8 * NN_];
__device__ int   g_cnt_out[8 * NN_];
__device__ int   g_cursor [8 * NN_];
__device__ int   g_off    [8 * (NN_ + 1)];
__device__ int   g_csr    [8 * EE_];
__device__ float g_din    [8 * NN_];
__device__ float g_dout   [8 * NN_];

// ---------------- tiny utility kernels -------------------------------------
__global__ void zero_int_kernel(int* p, int n) {
    for (int i = blockIdx.x * blockDim.x + threadIdx.x; i < n; i += gridDim.x * blockDim.x)
        p[i] = 0;
}

__global__ void hist_kernel(const int* __restrict__ src, const int* __restrict__ dst,
                            int* __restrict__ cnt_out, int* __restrict__ cnt_in, int e) {
    for (int i = blockIdx.x * blockDim.x + threadIdx.x; i < e; i += gridDim.x * blockDim.x) {
        atomicAdd(&cnt_out[src[i]], 1);
        atomicAdd(&cnt_in [dst[i]], 1);
    }
}

__global__ void deg_kernel(const int* __restrict__ cin, const int* __restrict__ cout,
                           float* __restrict__ din, float* __restrict__ dout, int n) {
    for (int i = blockIdx.x * blockDim.x + threadIdx.x; i < n; i += gridDim.x * blockDim.x) {
        int a = cin[i];  if (a < 1) a = 1;
        int b = cout[i]; if (b < 1) b = 1;
        din [i] = rsqrtf((float)a);
        dout[i] = rsqrtf((float)b);
    }
}

// single-block exclusive scan of cnt -> off (and cursor copy). n <= 1024*CH
__global__ void scan_kernel(const int* __restrict__ cnt, int* __restrict__ off,
                            int* __restrict__ cur, int n) {
    __shared__ int sh[1024];
    const int t  = threadIdx.x;
    const int CH = (n + 1023) / 1024;
    const int base = t * CH;
    int s = 0;
    for (int i = 0; i < CH; i++) { int idx = base + i; if (idx < n) s += cnt[idx]; }
    sh[t] = s;
    __syncthreads();
    for (int d = 1; d < 1024; d <<= 1) {
        int v = (t >= d) ? sh[t - d] : 0;
        __syncthreads();
        sh[t] += v;
        __syncthreads();
    }
    int run = (t == 0) ? 0 : sh[t - 1];
    for (int i = 0; i < CH; i++) {
        int idx = base + i;
        if (idx < n) { off[idx] = run; cur[idx] = run; run += cnt[idx]; }
    }
    if (t == 0) off[n] = sh[1023];
}

__global__ void scatter_kernel(const int* __restrict__ src, const int* __restrict__ dst,
                               int* __restrict__ cursor, int* __restrict__ csr, int e) {
    for (int i = blockIdx.x * blockDim.x + threadIdx.x; i < e; i += gridDim.x * blockDim.x) {
        int pos = atomicAdd(&cursor[dst[i]], 1);
        csr[pos] = src[i];
    }
}

// ---------------- CSR gather aggregation (warp per node) -------------------
// out[n,:] = sum_{e in csr[off[n]..off[n+1])} h[src_e,:] * dout[src_e]
__global__ void gather_kernel(const float* __restrict__ h, const int* __restrict__ off,
                              const int* __restrict__ csr, const float* __restrict__ dout,
                              float* __restrict__ out) {
    int warp = (blockIdx.x * blockDim.x + threadIdx.x) >> 5;
    int lane = threadIdx.x & 31;
    if (warp >= NN_) return;
    int b = off[warp], e = off[warp + 1];
    float a0 = 0.f, a1 = 0.f, a2 = 0.f, a3 = 0.f;
    for (int i = b; i < e; i++) {
        int s = csr[i];
        float w = dout[s];
        const float* hp = h + (size_t)s * HH_;
        a0 += w * hp[lane];
        a1 += w * hp[lane + 32];
        a2 += w * hp[lane + 64];
        a3 += w * hp[lane + 96];
    }
    float* op = out + (size_t)warp * HH_;
    op[lane]      = a0;
    op[lane + 32] = a1;
    op[lane + 64] = a2;
    op[lane + 96] = a3;
}

// ---------------- generic fp32 tiled GEMM with fused epilogues -------------
// C(MxBN..128) = A @ (TB ? B^T : B), A may be a 3-segment concat along K.
// EPI: 0 none, 1 tanh, 2 acc*rowscale[m]+bias[col], 3 tanh(acc+bias[col])
template <int BN, bool TB, int EPI>
__global__ __launch_bounds__(256)
void gemm_kernel(const float* __restrict__ A0, const float* __restrict__ A1,
                 const float* __restrict__ A2, int lda, int Ktotal,
                 const float* __restrict__ B, int ldb,
                 float* __restrict__ C, int ldc, int M,
                 const float* __restrict__ rowscale, const float* __restrict__ bias) {
    constexpr int BM = 128, BK = 16, TM = 8, TN = BN / 16;
    __shared__ float As[BK][BM];
    __shared__ float Bs[BK][BN];

    const int block_m = blockIdx.x * BM;
    const int tid = threadIdx.x;          // 256 threads
    const int tx = tid & 15;              // 16 cols of threads
    const int ty = tid >> 4;              // 16 rows of threads

    float acc[TM][TN];
#pragma unroll
    for (int i = 0; i < TM; i++)
#pragma unroll
        for (int j = 0; j < TN; j++) acc[i][j] = 0.f;

    for (int k0 = 0; k0 < Ktotal; k0 += BK) {
        // ---- load A tile (BM x BK), 8 elems per thread, rows contiguous in K
        const float* A = A0;
        int kseg = k0;
        if (A1 != nullptr) {              // 3-segment concat, each segment K=128
            int seg = k0 >> 7;
            kseg = k0 & 127;
            A = (seg == 0) ? A0 : ((seg == 1) ? A1 : A2);
        }
        {
            int row = tid >> 1;
            int kk = (tid & 1) * 8;
            int gm = block_m + row;
            const float* ap = A + (size_t)gm * lda + kseg + kk;
#pragma unroll
            for (int i = 0; i < 8; i++)
                As[kk + i][row] = (gm < M) ? ap[i] : 0.f;
        }
        // ---- load B tile
        if (TB) {
            if (BN == 128) {
                int j = tid >> 1;
                int kk = (tid & 1) * 8;
                const float* bp = B + (size_t)j * ldb + k0 + kk;
#pragma unroll
                for (int i = 0; i < 8; i++) Bs[kk + i][j] = bp[i];
            } else {
                int j = tid >> 2;
                int kk = (tid & 3) * 4;
                const float* bp = B + (size_t)j * ldb + k0 + kk;
#pragma unroll
                for (int i = 0; i < 4; i++) Bs[kk + i][j] = bp[i];
            }
        } else {
            if (BN == 128) {
                int kk = tid >> 4;
                int j0 = (tid & 15) * 8;
                const float* bp = B + (size_t)(k0 + kk) * ldb + j0;
#pragma unroll
                for (int i = 0; i < 8; i++) Bs[kk][j0 + i] = bp[i];
            } else {
                int kk = tid >> 4;
                int j0 = (tid & 15) * 4;
                const float* bp = B + (size_t)(k0 + kk) * ldb + j0;
#pragma unroll
                for (int i = 0; i < 4; i++) Bs[kk][j0 + i] = bp[i];
            }
        }
        __syncthreads();
#pragma unroll
        for (int k = 0; k < BK; k++) {
            float a[TM], b[TN];
#pragma unroll
            for (int i = 0; i < TM; i++) a[i] = As[k][ty + 16 * i];
#pragma unroll
            for (int j = 0; j < TN; j++) b[j] = Bs[k][tx + 16 * j];
#pragma unroll
            for (int i = 0; i < TM; i++)
#pragma unroll
                for (int j = 0; j < TN; j++) acc[i][j] += a[i] * b[j];
        }
        __syncthreads();
    }
    // ---- epilogue
#pragma unroll
    for (int i = 0; i < TM; i++) {
        int gm = block_m + ty + 16 * i;
        if (gm >= M) continue;
        float rs = (EPI == 2) ? rowscale[gm] : 1.f;
        float* cp = C + (size_t)gm * ldc;
#pragma unroll
        for (int j = 0; j < TN; j++) {
            int col = tx + 16 * j;
            float v = acc[i][j];
            if (EPI == 1) v = tanhf(v);
            else if (EPI == 2) v = v * rs + bias[col];
            else if (EPI == 3) v = tanhf(v + bias[col]);
            cp[col] = v;
        }
    }
}

// ---------------- attention combine (warp per node) ------------------------
// s_r[n] = sum_q t_r[n,q] * w2[q]; a = softmax over r; out = a0*hs0 + a1*hs1
__global__ void combine_kernel(const float* __restrict__ hs0, const float* __restrict__ hs1,
                               const float* __restrict__ t0, const float* __restrict__ t1,
                               const float* __restrict__ w2, float* __restrict__ out) {
    int warp = (blockIdx.x * blockDim.x + threadIdx.x) >> 5;
    int lane = threadIdx.x & 31;
    if (warp >= NN_) return;
    const float* p0 = t0 + (size_t)warp * QQ_;
    const float* p1 = t1 + (size_t)warp * QQ_;
    float w2a = w2[lane], w2b = w2[lane + 32];
    float s0 = p0[lane] * w2a + p0[lane + 32] * w2b;
    float s1 = p1[lane] * w2a + p1[lane + 32] * w2b;
#pragma unroll
    for (int o = 16; o; o >>= 1) {
        s0 += __shfl_xor_sync(0xffffffffu, s0, o);
        s1 += __shfl_xor_sync(0xffffffffu, s1, o);
    }
    float m = fmaxf(s0, s1);
    float e0 = expf(s0 - m), e1 = expf(s1 - m);
    float a0 = e0 / (e0 + e1), a1 = 1.f - a0;
    const float* h0p = hs0 + (size_t)warp * HH_;
    const float* h1p = hs1 + (size_t)warp * HH_;
    float* op = out + (size_t)warp * HH_;
#pragma unroll
    for (int k = 0; k < 4; k++) {
        int j = lane + 32 * k;
        op[j] = a0 * h0p[j] + a1 * h1p[j];
    }
}

// ---------------- host orchestration ---------------------------------------
static inline const int* edge_ptr(const int* edges, int sign, int r, int which /*0 src,1 dst*/) {
    // edges layout: (2, R=2, 2, E)
    return edges + ((size_t)((sign * 2 + r) * 2 + which)) * EE_;
}

extern "C" void kernel_launch(void* const* d_in, const int* in_sizes, int n_in,
                              void* d_out, int out_size) {
    const float* x_attr  = (const float*)d_in[0];
    const float* x_stru  = (const float*)d_in[1];
    const int*   e_attr  = (const int*)  d_in[2];
    const int*   e_stru  = (const int*)  d_in[3];
    const float* Wf      = (const float*)d_in[4];   // (2,H,F)
    const float* convW   = (const float*)d_in[5];   // (2,2,2,H,H)
    const float* convB   = (const float*)d_in[6];   // (2,2,2,H)
    const float* attnW1  = (const float*)d_in[7];   // (2,2,H,Q)
    const float* attnB1  = (const float*)d_in[8];   // (2,2,Q)
    const float* attnW2  = (const float*)d_in[9];   // (2,2,Q)
    const float* Wc      = (const float*)d_in[10];  // (2,H,3H)
    float* out = (float*)d_out;

    // resolve device-symbol addresses (host-side lookup, capture-safe)
    float *h0, *h1, *hA, *h2, *agg, *hs0, *hs1, *t0, *t1, *din, *dout;
    int *cnt_in, *cnt_out, *cursor, *off, *csr;
    cudaGetSymbolAddress((void**)&h0,  g_h0);
    cudaGetSymbolAddress((void**)&h1,  g_h1);
    cudaGetSymbolAddress((void**)&hA,  g_hA);
    cudaGetSymbolAddress((void**)&h2,  g_h2);
    cudaGetSymbolAddress((void**)&agg, g_agg);
    cudaGetSymbolAddress((void**)&hs0, g_hs0);
    cudaGetSymbolAddress((void**)&hs1, g_hs1);
    cudaGetSymbolAddress((void**)&t0,  g_t0);
    cudaGetSymbolAddress((void**)&t1,  g_t1);
    cudaGetSymbolAddress((void**)&din,  g_din);
    cudaGetSymbolAddress((void**)&dout, g_dout);
    cudaGetSymbolAddress((void**)&cnt_in,  g_cnt_in);
    cudaGetSymbolAddress((void**)&cnt_out, g_cnt_out);
    cudaGetSymbolAddress((void**)&cursor,  g_cursor);
    cudaGetSymbolAddress((void**)&off, g_off);
    cudaGetSymbolAddress((void**)&csr, g_csr);

    const int TB256 = 256;
    const int gridE = 1024;
    const int gridWarp = (NN_ + 7) / 8;       // warp-per-node kernels, 256 thr
    const int gridM = (NN_ + 127) / 128;      // GEMM blocks

    // ---- phase 1: build degrees + CSR for all 8 (combo, relation) pairs ----
    zero_int_kernel<<<512, TB256>>>(cnt_in, 8 * NN_);
    zero_int_kernel<<<512, TB256>>>(cnt_out, 8 * NN_);

    for (int c = 0; c < 4; c++) {
        int sign = c >> 1;
        const int* E = (c & 1) ? e_stru : e_attr;
        for (int r = 0; r < 2; r++) {
            int p = c * 2 + r;
            hist_kernel<<<gridE, TB256>>>(edge_ptr(E, sign, r, 0), edge_ptr(E, sign, r, 1),
                                          cnt_out + p * NN_, cnt_in + p * NN_, EE_);
        }
    }
    for (int p = 0; p < 8; p++) {
        deg_kernel<<<(NN_ + 255) / 256, TB256>>>(cnt_in + p * NN_, cnt_out + p * NN_,
                                                 din + p * NN_, dout + p * NN_, NN_);
        scan_kernel<<<1, 1024>>>(cnt_in + p * NN_, off + p * (NN_ + 1), cursor + p * NN_, NN_);
    }
    for (int c = 0; c < 4; c++) {
        int sign = c >> 1;
        const int* E = (c & 1) ? e_stru : e_attr;
        for (int r = 0; r < 2; r++) {
            int p = c * 2 + r;
            scatter_kernel<<<gridE, TB256>>>(edge_ptr(E, sign, r, 0), edge_ptr(E, sign, r, 1),
                                             cursor + p * NN_, csr + p * EE_, EE_);
        }
    }

    // ---- phase 2: the four runs ----
    for (int c = 0; c < 4; c++) {
        const int s = c >> 1;
        const float* x = (c & 1) ? x_stru : x_attr;

        // h0 = tanh(x @ Wf[s]^T)
        gemm_kernel<128, true, 1><<<gridM, TB256>>>(
            x, nullptr, nullptr, FF_, FF_,
            Wf + (size_t)s * HH_ * FF_, FF_, h0, HH_, NN_, nullptr, nullptr);

        // het layer helper (inline): (input, layer l, output)
        auto het = [&](const float* hin, int l, float* hout) {
            for (int r = 0; r < 2; r++) {
                int p = c * 2 + r;
                gather_kernel<<<gridWarp, TB256>>>(hin, off + p * (NN_ + 1),
                                                   csr + p * EE_, dout + p * NN_, agg);
                const float* W  = convW + (size_t)(((s * 2 + l) * 2 + r)) * HH_ * HH_;
                const float* b  = convB + (size_t)(((s * 2 + l) * 2 + r)) * HH_;
                float* hs = r ? hs1 : hs0;
                gemm_kernel<128, false, 2><<<gridM, TB256>>>(
                    agg, nullptr, nullptr, HH_, HH_, W, HH_, hs, HH_, NN_,
                    din + p * NN_, b);
                const float* W1 = attnW1 + (size_t)(s * 2 + l) * HH_ * QQ_;
                const float* b1 = attnB1 + (size_t)(s * 2 + l) * QQ_;
                gemm_kernel<64, false, 3><<<gridM, TB256>>>(
                    hs, nullptr, nullptr, HH_, HH_, W1, QQ_, r ? t1 : t0, QQ_, NN_,
                    nullptr, b1);
            }
            const float* w2 = attnW2 + (size_t)(s * 2 + l) * QQ_;
            combine_kernel<<<gridWarp, TB256>>>(hs0, hs1, t0, t1, w2, hout);
        };

        het(h0, 1, h1);   // 1-hop via last conv layer
        het(h0, 0, hA);
        het(hA, 1, h2);   // 2-hop

        // y = [h0|h1|h2] @ Wc[s]^T  -> output slice c
        gemm_kernel<128, true, 0><<<gridM, TB256>>>(
            h0, h1, h2, HH_, 3 * HH_,
            Wc + (size_t)s * HH_ * 3 * HH_, 3 * HH_,
            out + (size_t)c * NN_ * HH_, HH_, NN_, nullptr, nullptr);
    }
}

// round 2
// speedup vs baseline: 1.6833x; 1.6833x over previous
#include <cuda_runtime.h>
#include <math.h>

// Problem constants
#define NN_ 50000
#define EE_ 600000
#define HH_ 128
#define FF_ 256
#define QQ_ 64

// ---------------- scratch (device globals; no dynamic allocation) ----------
__device__ float g_h0 [NN_ * HH_];
__device__ float g_h1 [NN_ * HH_];
__device__ float g_hA [NN_ * HH_];
__device__ float g_h2 [NN_ * HH_];
__device__ float g_agg[NN_ * HH_];
__device__ float g_hs0[NN_ * HH_];
__device__ float g_hs1[NN_ * HH_];
__device__ float g_t0 [NN_ * QQ_];
__device__ float g_t1 [NN_ * QQ_];

__device__ int   g_cnt_in [8 * NN_];
__device__ int   g_cnt_out[8 * NN_];
__device__ int   g_cursor [8 * NN_];
__device__ int   g_off    [8 * (NN_ + 1)];
__device__ int   g_csr    [8 * EE_];
__device__ float g_din    [8 * NN_];
__device__ float g_dout   [8 * NN_];

// ---------------- tiny utility kernels -------------------------------------
__global__ void zero_int_kernel(int* p, int n) {
    for (int i = blockIdx.x * blockDim.x + threadIdx.x; i < n; i += gridDim.x * blockDim.x)
        p[i] = 0;
}

__global__ void hist_kernel(const int* __restrict__ src, const int* __restrict__ dst,
                            int* __restrict__ cnt_out, int* __restrict__ cnt_in, int e) {
    for (int i = blockIdx.x * blockDim.x + threadIdx.x; i < e; i += gridDim.x * blockDim.x) {
        atomicAdd(&cnt_out[src[i]], 1);
        atomicAdd(&cnt_in [dst[i]], 1);
    }
}

__global__ void deg_kernel(const int* __restrict__ cin, const int* __restrict__ cout,
                           float* __restrict__ din, float* __restrict__ dout, int n) {
    for (int i = blockIdx.x * blockDim.x + threadIdx.x; i < n; i += gridDim.x * blockDim.x) {
        int a = cin[i];  if (a < 1) a = 1;
        int b = cout[i]; if (b < 1) b = 1;
        din [i] = rsqrtf((float)a);
        dout[i] = rsqrtf((float)b);
    }
}

// single-block exclusive scan of cnt -> off (and cursor copy)
__global__ void scan_kernel(const int* __restrict__ cnt, int* __restrict__ off,
                            int* __restrict__ cur, int n) {
    __shared__ int sh[1024];
    const int t  = threadIdx.x;
    const int CH = (n + 1023) / 1024;
    const int base = t * CH;
    int s = 0;
    for (int i = 0; i < CH; i++) { int idx = base + i; if (idx < n) s += cnt[idx]; }
    sh[t] = s;
    __syncthreads();
    for (int d = 1; d < 1024; d <<= 1) {
        int v = (t >= d) ? sh[t - d] : 0;
        __syncthreads();
        sh[t] += v;
        __syncthreads();
    }
    int run = (t == 0) ? 0 : sh[t - 1];
    for (int i = 0; i < CH; i++) {
        int idx = base + i;
        if (idx < n) { off[idx] = run; cur[idx] = run; run += cnt[idx]; }
    }
    if (t == 0) off[n] = sh[1023];
}

__global__ void scatter_kernel(const int* __restrict__ src, const int* __restrict__ dst,
                               int* __restrict__ cursor, int* __restrict__ csr, int e) {
    for (int i = blockIdx.x * blockDim.x + threadIdx.x; i < e; i += gridDim.x * blockDim.x) {
        int pos = atomicAdd(&cursor[dst[i]], 1);
        csr[pos] = src[i];
    }
}

// ---------------- CSR gather aggregation (warp per node, float4) -----------
__global__ void gather_kernel(const float* __restrict__ h, const int* __restrict__ off,
                              const int* __restrict__ csr, const float* __restrict__ dout,
                              float* __restrict__ out) {
    int warp = (blockIdx.x * blockDim.x + threadIdx.x) >> 5;
    int lane = threadIdx.x & 31;
    if (warp >= NN_) return;
    int b = off[warp], e = off[warp + 1];
    const float4* h4 = (const float4*)h;
    float ax = 0.f, ay = 0.f, az = 0.f, aw = 0.f;
    int i = b;
    for (; i + 1 < e; i += 2) {
        int s0 = csr[i], s1 = csr[i + 1];
        float w0 = dout[s0], w1 = dout[s1];
        float4 v0 = h4[(size_t)s0 * 32 + lane];
        float4 v1 = h4[(size_t)s1 * 32 + lane];
        ax += w0 * v0.x + w1 * v1.x;
        ay += w0 * v0.y + w1 * v1.y;
        az += w0 * v0.z + w1 * v1.z;
        aw += w0 * v0.w + w1 * v1.w;
    }
    if (i < e) {
        int s0 = csr[i];
        float w0 = dout[s0];
        float4 v0 = h4[(size_t)s0 * 32 + lane];
        ax += w0 * v0.x; ay += w0 * v0.y; az += w0 * v0.z; aw += w0 * v0.w;
    }
    float4 r; r.x = ax; r.y = ay; r.z = az; r.w = aw;
    ((float4*)out)[(size_t)warp * 32 + lane] = r;
}

// ---------------- tf32 tensor-core GEMM with fused epilogues ---------------
// C(M x BN) = A @ (TB ? B^T : B). A may be a 3-segment concat along K (seg K=128).
// EPI: 0 none, 1 tanh, 2 acc*rowscale[m]+bias[col], 3 tanh(acc+bias[col])
__device__ __forceinline__ unsigned f2tf(float f) {
    unsigned u;
    asm("cvt.rna.tf32.f32 %0, %1;" : "=r"(u) : "f"(f));
    return u;
}

__device__ __forceinline__ void mma8(float* c, const unsigned* a, unsigned b0, unsigned b1) {
    asm volatile(
        "mma.sync.aligned.m16n8k8.row.col.f32.tf32.tf32.f32 "
        "{%0,%1,%2,%3},{%4,%5,%6,%7},{%8,%9},{%0,%1,%2,%3};"
        : "+f"(c[0]), "+f"(c[1]), "+f"(c[2]), "+f"(c[3])
        : "r"(a[0]), "r"(a[1]), "r"(a[2]), "r"(a[3]), "r"(b0), "r"(b1));
}

template <int BN, bool TB, int EPI>
__global__ __launch_bounds__(256)
void gemm_tc_kernel(const float* __restrict__ A0, const float* __restrict__ A1,
                    const float* __restrict__ A2, int lda, int Ktotal,
                    const float* __restrict__ B, int ldb,
                    float* __restrict__ C, int ldc, int M,
                    const float* __restrict__ rowscale, const float* __restrict__ bias) {
    constexpr int BM = 128, BK = 32;
    constexpr int LDS_ = 136;              // pad 8: bank = 8*tig + grp -> conflict-free
    constexpr int WN = BN / 2;             // warp n-extent (8 warps: 4 m x 2 n)
    constexpr int NF = WN / 8;

    __shared__ unsigned As[BK][LDS_];
    __shared__ unsigned Bs[BK][LDS_];

    const int tid  = threadIdx.x;
    const int lane = tid & 31;
    const int warp = tid >> 5;
    const int grp  = lane >> 2;            // 0..7
    const int tig  = lane & 3;             // 0..3
    const int wm   = warp >> 1;            // 0..3 -> 32 rows each
    const int wn   = warp & 1;             // 0..1
    const int mbase = wm * 32;
    const int nbase = wn * WN;
    const int block_m = blockIdx.x * BM;

    float acc[2][NF][4];
#pragma unroll
    for (int mf = 0; mf < 2; mf++)
#pragma unroll
        for (int nf = 0; nf < NF; nf++)
#pragma unroll
            for (int q = 0; q < 4; q++) acc[mf][nf][q] = 0.f;

    for (int k0 = 0; k0 < Ktotal; k0 += BK) {
        // ---- select A segment (3-seg concat support)
        const float* A = A0;
        int kseg = k0;
        if (A1 != nullptr) {
            int seg = k0 >> 7;
            kseg = k0 & 127;
            A = (seg == 0) ? A0 : ((seg == 1) ? A1 : A2);
        }
        // ---- A tile: 128 rows x 32 k, stored transposed As[k][m] as tf32 bits
        {
            int row = tid & 127;
            int f4b = tid >> 7;            // 0..1
            int gm = block_m + row;
            bool ok = (gm < M);
            const float* ap = A + (size_t)gm * lda + kseg;
#pragma unroll
            for (int ii = 0; ii < 4; ii++) {
                int f4 = f4b + ii * 2;
                float4 v;
                if (ok) v = *(const float4*)(ap + f4 * 4);
                else { v.x = v.y = v.z = v.w = 0.f; }
                int kc = f4 * 4;
                As[kc + 0][row] = f2tf(v.x);
                As[kc + 1][row] = f2tf(v.y);
                As[kc + 2][row] = f2tf(v.z);
                As[kc + 3][row] = f2tf(v.w);
            }
        }
        // ---- B tile -> Bs[k][n]
        if (TB) {
            // B is (BN x K) row-major; transpose on load. (only used with BN=128)
            int n = tid & 127;
            int f4b = tid >> 7;
            const float* bp = B + (size_t)n * ldb + k0;
#pragma unroll
            for (int ii = 0; ii < 4; ii++) {
                int f4 = f4b + ii * 2;
                float4 v = *(const float4*)(bp + f4 * 4);
                int kc = f4 * 4;
                Bs[kc + 0][n] = f2tf(v.x);
                Bs[kc + 1][n] = f2tf(v.y);
                Bs[kc + 2][n] = f2tf(v.z);
                Bs[kc + 3][n] = f2tf(v.w);
            }
        } else if (BN == 128) {
            // B is (K x 128) row-major; direct copy
            int f4 = tid & 31;
            int kb = tid >> 5;             // 0..7
#pragma unroll
            for (int ii = 0; ii < 4; ii++) {
                int k = kb + ii * 8;
                float4 v = *(const float4*)(B + (size_t)(k0 + k) * ldb + f4 * 4);
                uint4 w;
                w.x = f2tf(v.x); w.y = f2tf(v.y); w.z = f2tf(v.z); w.w = f2tf(v.w);
                *(uint4*)&Bs[k][f4 * 4] = w;
            }
        } else {
            // BN == 64, (K x 64) row-major
            int f4 = tid & 15;
            int kb = tid >> 4;             // 0..15
#pragma unroll
            for (int ii = 0; ii < 2; ii++) {
                int k = kb + ii * 16;
                float4 v = *(const float4*)(B + (size_t)(k0 + k) * ldb + f4 * 4);
                uint4 w;
                w.x = f2tf(v.x); w.y = f2tf(v.y); w.z = f2tf(v.z); w.w = f2tf(v.w);
                *(uint4*)&Bs[k][f4 * 4] = w;
            }
        }
        __syncthreads();

        // ---- compute: 4 k8 steps
#pragma unroll
        for (int k8 = 0; k8 < BK; k8 += 8) {
            unsigned a[2][4];
#pragma unroll
            for (int mf = 0; mf < 2; mf++) {
                int r0 = mbase + mf * 16 + grp;
                a[mf][0] = As[k8 + tig][r0];
                a[mf][1] = As[k8 + tig][r0 + 8];
                a[mf][2] = As[k8 + tig + 4][r0];
                a[mf][3] = As[k8 + tig + 4][r0 + 8];
            }
#pragma unroll
            for (int nf = 0; nf < NF; nf++) {
                int n = nbase + nf * 8 + grp;
                unsigned b0 = Bs[k8 + tig][n];
                unsigned b1 = Bs[k8 + tig + 4][n];
                mma8(acc[0][nf], a[0], b0, b1);
                mma8(acc[1][nf], a[1], b0, b1);
            }
        }
        __syncthreads();
    }

    // ---- epilogue
#pragma unroll
    for (int mf = 0; mf < 2; mf++) {
        int r0 = block_m + mbase + mf * 16 + grp;   // rows r0 and r0+8
#pragma unroll
        for (int nf = 0; nf < NF; nf++) {
            int col = nbase + nf * 8 + tig * 2;
            float bc0 = 0.f, bc1 = 0.f;
            if (EPI == 2 || EPI == 3) { bc0 = bias[col]; bc1 = bias[col + 1]; }
#pragma unroll
            for (int half = 0; half < 2; half++) {
                int r = r0 + half * 8;
                if (r >= M) continue;
                float v0 = acc[mf][nf][half * 2 + 0];
                float v1 = acc[mf][nf][half * 2 + 1];
                if (EPI == 1) { v0 = tanhf(v0); v1 = tanhf(v1); }
                else if (EPI == 2) {
                    float rs = rowscale[r];
                    v0 = v0 * rs + bc0; v1 = v1 * rs + bc1;
                } else if (EPI == 3) {
                    v0 = tanhf(v0 + bc0); v1 = tanhf(v1 + bc1);
                }
                float2 st; st.x = v0; st.y = v1;
                *(float2*)(C + (size_t)r * ldc + col) = st;
            }
        }
    }
}

// ---------------- attention combine (warp per node) ------------------------
__global__ void combine_kernel(const float* __restrict__ hs0, const float* __restrict__ hs1,
                               const float* __restrict__ t0, const float* __restrict__ t1,
                               const float* __restrict__ w2, float* __restrict__ out) {
    int warp = (blockIdx.x * blockDim.x + threadIdx.x) >> 5;
    int lane = threadIdx.x & 31;
    if (warp >= NN_) return;
    const float* p0 = t0 + (size_t)warp * QQ_;
    const float* p1 = t1 + (size_t)warp * QQ_;
    float w2a = w2[lane], w2b = w2[lane + 32];
    float s0 = p0[lane] * w2a + p0[lane + 32] * w2b;
    float s1 = p1[lane] * w2a + p1[lane + 32] * w2b;
#pragma unroll
    for (int o = 16; o; o >>= 1) {
        s0 += __shfl_xor_sync(0xffffffffu, s0, o);
        s1 += __shfl_xor_sync(0xffffffffu, s1, o);
    }
    float m = fmaxf(s0, s1);
    float e0 = expf(s0 - m), e1 = expf(s1 - m);
    float a0 = e0 / (e0 + e1), a1 = 1.f - a0;
    const float4* h0p = (const float4*)(hs0 + (size_t)warp * HH_);
    const float4* h1p = (const float4*)(hs1 + (size_t)warp * HH_);
    float4* op = (float4*)(out + (size_t)warp * HH_);
    float4 u = h0p[lane & 31];
    // each lane handles 4 contiguous floats at index lane (32 lanes x 4 = 128)
    float4 v = h1p[lane];
    u = h0p[lane];
    float4 r;
    r.x = a0 * u.x + a1 * v.x;
    r.y = a0 * u.y + a1 * v.y;
    r.z = a0 * u.z + a1 * v.z;
    r.w = a0 * u.w + a1 * v.w;
    op[lane] = r;
}

// ---------------- host orchestration ---------------------------------------
static inline const int* edge_ptr(const int* edges, int sign, int r, int which) {
    return edges + ((size_t)((sign * 2 + r) * 2 + which)) * EE_;
}

extern "C" void kernel_launch(void* const* d_in, const int* in_sizes, int n_in,
                              void* d_out, int out_size) {
    const float* x_attr  = (const float*)d_in[0];
    const float* x_stru  = (const float*)d_in[1];
    const int*   e_attr  = (const int*)  d_in[2];
    const int*   e_stru  = (const int*)  d_in[3];
    const float* Wf      = (const float*)d_in[4];   // (2,H,F)
    const float* convW   = (const float*)d_in[5];   // (2,2,2,H,H)
    const float* convB   = (const float*)d_in[6];   // (2,2,2,H)
    const float* attnW1  = (const float*)d_in[7];   // (2,2,H,Q)
    const float* attnB1  = (const float*)d_in[8];   // (2,2,Q)
    const float* attnW2  = (const float*)d_in[9];   // (2,2,Q)
    const float* Wc      = (const float*)d_in[10];  // (2,H,3H)
    float* out = (float*)d_out;

    float *h0, *h1, *hA, *h2, *agg, *hs0, *hs1, *t0, *t1, *din, *dout;
    int *cnt_in, *cnt_out, *cursor, *off, *csr;
    cudaGetSymbolAddress((void**)&h0,  g_h0);
    cudaGetSymbolAddress((void**)&h1,  g_h1);
    cudaGetSymbolAddress((void**)&hA,  g_hA);
    cudaGetSymbolAddress((void**)&h2,  g_h2);
    cudaGetSymbolAddress((void**)&agg, g_agg);
    cudaGetSymbolAddress((void**)&hs0, g_hs0);
    cudaGetSymbolAddress((void**)&hs1, g_hs1);
    cudaGetSymbolAddress((void**)&t0,  g_t0);
    cudaGetSymbolAddress((void**)&t1,  g_t1);
    cudaGetSymbolAddress((void**)&din,  g_din);
    cudaGetSymbolAddress((void**)&dout, g_dout);
    cudaGetSymbolAddress((void**)&cnt_in,  g_cnt_in);
    cudaGetSymbolAddress((void**)&cnt_out, g_cnt_out);
    cudaGetSymbolAddress((void**)&cursor,  g_cursor);
    cudaGetSymbolAddress((void**)&off, g_off);
    cudaGetSymbolAddress((void**)&csr, g_csr);

    const int TB256 = 256;
    const int gridE = 1024;
    const int gridWarp = (NN_ + 7) / 8;
    const int gridM = (NN_ + 127) / 128;

    // ---- phase 1: degrees + CSR for all 8 (combo, relation) pairs ----
    zero_int_kernel<<<512, TB256>>>(cnt_in, 8 * NN_);
    zero_int_kernel<<<512, TB256>>>(cnt_out, 8 * NN_);

    for (int c = 0; c < 4; c++) {
        int sign = c >> 1;
        const int* E = (c & 1) ? e_stru : e_attr;
        for (int r = 0; r < 2; r++) {
            int p = c * 2 + r;
            hist_kernel<<<gridE, TB256>>>(edge_ptr(E, sign, r, 0), edge_ptr(E, sign, r, 1),
                                          cnt_out + p * NN_, cnt_in + p * NN_, EE_);
        }
    }
    for (int p = 0; p < 8; p++) {
        deg_kernel<<<(NN_ + 255) / 256, TB256>>>(cnt_in + p * NN_, cnt_out + p * NN_,
                                                 din + p * NN_, dout + p * NN_, NN_);
        scan_kernel<<<1, 1024>>>(cnt_in + p * NN_, off + p * (NN_ + 1), cursor + p * NN_, NN_);
    }
    for (int c = 0; c < 4; c++) {
        int sign = c >> 1;
        const int* E = (c & 1) ? e_stru : e_attr;
        for (int r = 0; r < 2; r++) {
            int p = c * 2 + r;
            scatter_kernel<<<gridE, TB256>>>(edge_ptr(E, sign, r, 0), edge_ptr(E, sign, r, 1),
                                             cursor + p * NN_, csr + p * EE_, EE_);
        }
    }

    // ---- phase 2: the four runs ----
    for (int c = 0; c < 4; c++) {
        const int s = c >> 1;
        const float* x = (c & 1) ? x_stru : x_attr;

        // h0 = tanh(x @ Wf[s]^T)
        gemm_tc_kernel<128, true, 1><<<gridM, TB256>>>(
            x, nullptr, nullptr, FF_, FF_,
            Wf + (size_t)s * HH_ * FF_, FF_, h0, HH_, NN_, nullptr, nullptr);

        auto het = [&](const float* hin, int l, float* hout) {
            for (int r = 0; r < 2; r++) {
                int p = c * 2 + r;
                gather_kernel<<<gridWarp, TB256>>>(hin, off + p * (NN_ + 1),
                                                   csr + p * EE_, dout + p * NN_, agg);
                const float* W  = convW + (size_t)(((s * 2 + l) * 2 + r)) * HH_ * HH_;
                const float* b  = convB + (size_t)(((s * 2 + l) * 2 + r)) * HH_;
                float* hs = r ? hs1 : hs0;
                gemm_tc_kernel<128, false, 2><<<gridM, TB256>>>(
                    agg, nullptr, nullptr, HH_, HH_, W, HH_, hs, HH_, NN_,
                    din + p * NN_, b);
                const float* W1 = attnW1 + (size_t)(s * 2 + l) * HH_ * QQ_;
                const float* b1 = attnB1 + (size_t)(s * 2 + l) * QQ_;
                gemm_tc_kernel<64, false, 3><<<gridM, TB256>>>(
                    hs, nullptr, nullptr, HH_, HH_, W1, QQ_, r ? t1 : t0, QQ_, NN_,
                    nullptr, b1);
            }
            const float* w2 = attnW2 + (size_t)(s * 2 + l) * QQ_;
            combine_kernel<<<gridWarp, TB256>>>(hs0, hs1, t0, t1, w2, hout);
        };

        het(h0, 1, h1);   // 1-hop via last conv layer
        het(h0, 0, hA);
        het(hA, 1, h2);   // 2-hop

        // y = [h0|h1|h2] @ Wc[s]^T
        gemm_tc_kernel<128, true, 0><<<gridM, TB256>>>(
            h0, h1, h2, HH_, 3 * HH_,
            Wc + (size_t)s * HH_ * 3 * HH_, 3 * HH_,
            out + (size_t)c * NN_ * HH_, HH_, NN_, nullptr, nullptr);
    }
}

// round 4
// speedup vs baseline: 3.0028x; 1.7838x over previous
#include <cuda_runtime.h>
#include <math.h>

// Problem constants
#define NN_ 50000
#define EE_ 600000
#define HH_ 128
#define FF_ 256
#define QQ_ 64
#define NH_ (NN_ * HH_)

// ---------------- scratch (device globals; no dynamic allocation) ----------
__device__ float g_h0 [4 * NH_];
__device__ float g_h1 [4 * NH_];
__device__ float g_hA [4 * NH_];
__device__ float g_h2 [4 * NH_];
__device__ float g_agg[8 * NH_];     // (c,r) pairs; reused for phase A and B
__device__ float g_hs [16 * NH_];    // phase A: 16 combos; phase B reuses first 8
__device__ float g_s  [16 * NN_];

__device__ int   g_cnt_in [8 * NN_];
__device__ int   g_cnt_out[8 * NN_];
__device__ int   g_cursor [8 * NN_];
__device__ int   g_off    [8 * (NN_ + 1)];
__device__ int   g_csr    [8 * EE_];
__device__ float g_din    [8 * NN_];
__device__ float g_dout   [8 * NN_];

// ---------------- helpers ---------------------------------------------------
__device__ __forceinline__ const int* edge_ptr_dev(const int* e_attr, const int* e_stru,
                                                   int p, int which) {
    int c = p >> 1, r = p & 1;
    int sign = c >> 1;
    const int* E = (c & 1) ? e_stru : e_attr;
    return E + ((size_t)((sign * 2 + r) * 2 + which)) * EE_;
}

// ---------------- CSR-build kernels (batched over 8 pairs) ------------------
__global__ void zero_int_kernel(int* p, int n) {
    for (int i = blockIdx.x * blockDim.x + threadIdx.x; i < n; i += gridDim.x * blockDim.x)
        p[i] = 0;
}

__global__ void hist_all_kernel(const int* __restrict__ e_attr, const int* __restrict__ e_stru,
                                int* __restrict__ cnt_out, int* __restrict__ cnt_in) {
    int p = blockIdx.y;
    const int* src = edge_ptr_dev(e_attr, e_stru, p, 0);
    const int* dst = edge_ptr_dev(e_attr, e_stru, p, 1);
    int* co = cnt_out + p * NN_;
    int* ci = cnt_in  + p * NN_;
    for (int i = blockIdx.x * blockDim.x + threadIdx.x; i < EE_; i += gridDim.x * blockDim.x) {
        atomicAdd(&co[src[i]], 1);
        atomicAdd(&ci[dst[i]], 1);
    }
}

__global__ void deg_all_kernel(const int* __restrict__ cin, const int* __restrict__ cout,
                               float* __restrict__ din, float* __restrict__ dout) {
    for (int i = blockIdx.x * blockDim.x + threadIdx.x; i < 8 * NN_; i += gridDim.x * blockDim.x) {
        int a = cin[i];  if (a < 1) a = 1;
        int b = cout[i]; if (b < 1) b = 1;
        din [i] = rsqrtf((float)a);
        dout[i] = rsqrtf((float)b);
    }
}

// 8 blocks; block p scans its pair's counts
__global__ void scan_all_kernel(const int* __restrict__ cnt_all, int* __restrict__ off_all,
                                int* __restrict__ cur_all) {
    __shared__ int sh[1024];
    const int p = blockIdx.x;
    const int* cnt = cnt_all + p * NN_;
    int* off = off_all + p * (NN_ + 1);
    int* cur = cur_all + p * NN_;
    const int t  = threadIdx.x;
    const int CH = (NN_ + 1023) / 1024;
    const int base = t * CH;
    int s = 0;
    for (int i = 0; i < CH; i++) { int idx = base + i; if (idx < NN_) s += cnt[idx]; }
    sh[t] = s;
    __syncthreads();
    for (int d = 1; d < 1024; d <<= 1) {
        int v = (t >= d) ? sh[t - d] : 0;
        __syncthreads();
        sh[t] += v;
        __syncthreads();
    }
    int run = (t == 0) ? 0 : sh[t - 1];
    for (int i = 0; i < CH; i++) {
        int idx = base + i;
        if (idx < NN_) { off[idx] = run; cur[idx] = run; run += cnt[idx]; }
    }
    if (t == 0) off[NN_] = sh[1023];
}

__global__ void scatter_all_kernel(const int* __restrict__ e_attr, const int* __restrict__ e_stru,
                                   int* __restrict__ cursor, int* __restrict__ csr) {
    int p = blockIdx.y;
    const int* src = edge_ptr_dev(e_attr, e_stru, p, 0);
    const int* dst = edge_ptr_dev(e_attr, e_stru, p, 1);
    int* cu = cursor + p * NN_;
    int* cs = csr + (size_t)p * EE_;
    for (int i = blockIdx.x * blockDim.x + threadIdx.x; i < EE_; i += gridDim.x * blockDim.x) {
        int pos = atomicAdd(&cu[dst[i]], 1);
        cs[pos] = src[i];
    }
}

// ---------------- batched CSR gather (warp per node, float4) ----------------
// blockIdx.y = p in 0..7 (c = p>>1); hin = hin_base + c*NH_; out = agg + p*NH_
__global__ void gather_all_kernel(const float* __restrict__ hin_base,
                                  const int* __restrict__ off_all,
                                  const int* __restrict__ csr_all,
                                  const float* __restrict__ dout_all,
                                  float* __restrict__ agg) {
    int p = blockIdx.y;
    int c = p >> 1;
    const float* h = hin_base + (size_t)c * NH_;
    const int* off = off_all + p * (NN_ + 1);
    const int* csr = csr_all + (size_t)p * EE_;
    const float* dout = dout_all + p * NN_;
    float* out = agg + (size_t)p * NH_;

    int warp = (blockIdx.x * blockDim.x + threadIdx.x) >> 5;
    int lane = threadIdx.x & 31;
    if (warp >= NN_) return;
    int b = off[warp], e = off[warp + 1];
    const float4* h4 = (const float4*)h;
    float ax = 0.f, ay = 0.f, az = 0.f, aw = 0.f;
    int i = b;
    for (; i + 1 < e; i += 2) {
        int s0 = csr[i], s1 = csr[i + 1];
        float w0 = dout[s0], w1 = dout[s1];
        float4 v0 = h4[(size_t)s0 * 32 + lane];
        float4 v1 = h4[(size_t)s1 * 32 + lane];
        ax += w0 * v0.x + w1 * v1.x;
        ay += w0 * v0.y + w1 * v1.y;
        az += w0 * v0.z + w1 * v1.z;
        aw += w0 * v0.w + w1 * v1.w;
    }
    if (i < e) {
        int s0 = csr[i];
        float w0 = dout[s0];
        float4 v0 = h4[(size_t)s0 * 32 + lane];
        ax += w0 * v0.x; ay += w0 * v0.y; az += w0 * v0.z; aw += w0 * v0.w;
    }
    float4 r; r.x = ax; r.y = ay; r.z = az; r.w = aw;
    ((float4*)out)[(size_t)warp * 32 + lane] = r;
}

// ---------------- tf32 helpers ----------------------------------------------
__device__ __forceinline__ unsigned f2tf(float f) {
    unsigned u;
    asm("cvt.rna.tf32.f32 %0, %1;" : "=r"(u) : "f"(f));
    return u;
}

__device__ __forceinline__ void mma8(float* c, const unsigned* a, unsigned b0, unsigned b1) {
    asm volatile(
        "mma.sync.aligned.m16n8k8.row.col.f32.tf32.tf32.f32 "
        "{%0,%1,%2,%3},{%4,%5,%6,%7},{%8,%9},{%0,%1,%2,%3};"
        : "+f"(c[0]), "+f"(c[1]), "+f"(c[2]), "+f"(c[3])
        : "r"(a[0]), "r"(a[1]), "r"(a[2]), "r"(a[3]), "r"(b0), "r"(b1));
}

// ---------------- batched dense GEMM (h0 and final), C = A @ B^T ------------
// MODE 0: per-run h0 = tanh(x @ Wf[s]^T), K=256
// MODE 1: per-run y = [h0|h1|h2] @ Wc[s]^T, K=384 (3 segments of 128)
template <int MODE>
__global__ __launch_bounds__(256)
void gemm_all_kernel(const float* __restrict__ x_attr, const float* __restrict__ x_stru,
                     const float* __restrict__ Wf, const float* __restrict__ Wc,
                     const float* __restrict__ h0b, const float* __restrict__ h1b,
                     const float* __restrict__ h2b, float* __restrict__ Cout) {
    constexpr int BM = 128, BK = 32, LDS_ = 136, NF = 8;
    __shared__ unsigned As[BK][LDS_];
    __shared__ unsigned Bs[BK][LDS_];

    const int c = blockIdx.y;
    const int s = c >> 1;
    const int Ktotal = (MODE == 0) ? FF_ : 3 * HH_;
    const int lda = (MODE == 0) ? FF_ : HH_;
    const int ldb = Ktotal;
    const float* B = (MODE == 0) ? (Wf + (size_t)s * HH_ * FF_)
                                 : (Wc + (size_t)s * HH_ * 3 * HH_);
    float* C = (MODE == 0) ? ((float*)h0b + (size_t)c * NH_)   // h0 out (cast ok: passed as h0b)
                           : (Cout + (size_t)c * NH_);

    const int tid  = threadIdx.x;
    const int lane = tid & 31;
    const int warp = tid >> 5;
    const int grp  = lane >> 2;
    const int tig  = lane & 3;
    const int wm   = warp >> 1;
    const int wn   = warp & 1;
    const int mbase = wm * 32;
    const int nbase = wn * 64;
    const int block_m = blockIdx.x * BM;

    float acc[2][NF][4];
#pragma unroll
    for (int mf = 0; mf < 2; mf++)
#pragma unroll
        for (int nf = 0; nf < NF; nf++)
#pragma unroll
            for (int q = 0; q < 4; q++) acc[mf][nf][q] = 0.f;

    for (int k0 = 0; k0 < Ktotal; k0 += BK) {
        const float* A;
        int kseg;
        if (MODE == 0) {
            A = ((c & 1) ? x_stru : x_attr);
            kseg = k0;
        } else {
            int seg = k0 >> 7;
            kseg = k0 & 127;
            const float* base = (seg == 0) ? h0b : ((seg == 1) ? h1b : h2b);
            A = base + (size_t)c * NH_;
        }
        {
            int row = tid & 127;
            int f4b = tid >> 7;
            int gm = block_m + row;
            bool ok = (gm < NN_);
            const float* ap = A + (size_t)gm * lda + kseg;
#pragma unroll
            for (int ii = 0; ii < 4; ii++) {
                int f4 = f4b + ii * 2;
                float4 v;
                if (ok) v = *(const float4*)(ap + f4 * 4);
                else { v.x = v.y = v.z = v.w = 0.f; }
                int kc = f4 * 4;
                As[kc + 0][row] = f2tf(v.x);
                As[kc + 1][row] = f2tf(v.y);
                As[kc + 2][row] = f2tf(v.z);
                As[kc + 3][row] = f2tf(v.w);
            }
        }
        {
            int n = tid & 127;
            int f4b = tid >> 7;
            const float* bp = B + (size_t)n * ldb + k0;
#pragma unroll
            for (int ii = 0; ii < 4; ii++) {
                int f4 = f4b + ii * 2;
                float4 v = *(const float4*)(bp + f4 * 4);
                int kc = f4 * 4;
                Bs[kc + 0][n] = f2tf(v.x);
                Bs[kc + 1][n] = f2tf(v.y);
                Bs[kc + 2][n] = f2tf(v.z);
                Bs[kc + 3][n] = f2tf(v.w);
            }
        }
        __syncthreads();
#pragma unroll
        for (int k8 = 0; k8 < BK; k8 += 8) {
            unsigned a[2][4];
#pragma unroll
            for (int mf = 0; mf < 2; mf++) {
                int r0 = mbase + mf * 16 + grp;
                a[mf][0] = As[k8 + tig][r0];
                a[mf][1] = As[k8 + tig][r0 + 8];
                a[mf][2] = As[k8 + tig + 4][r0];
                a[mf][3] = As[k8 + tig + 4][r0 + 8];
            }
#pragma unroll
            for (int nf = 0; nf < NF; nf++) {
                int n = nbase + nf * 8 + grp;
                unsigned b0 = Bs[k8 + tig][n];
                unsigned b1 = Bs[k8 + tig + 4][n];
                mma8(acc[0][nf], a[0], b0, b1);
                mma8(acc[1][nf], a[1], b0, b1);
            }
        }
        __syncthreads();
    }
#pragma unroll
    for (int mf = 0; mf < 2; mf++) {
        int r0 = block_m + mbase + mf * 16 + grp;
#pragma unroll
        for (int nf = 0; nf < NF; nf++) {
            int col = nbase + nf * 8 + tig * 2;
#pragma unroll
            for (int half = 0; half < 2; half++) {
                int r = r0 + half * 8;
                if (r >= NN_) continue;
                float v0 = acc[mf][nf][half * 2 + 0];
                float v1 = acc[mf][nf][half * 2 + 1];
                if (MODE == 0) { v0 = tanhf(v0); v1 = tanhf(v1); }
                float2 st; st.x = v0; st.y = v1;
                *(float2*)(C + (size_t)r * HH_ + col) = st;
            }
        }
    }
}

// ---------------- batched fused conv GEMM + attention score -----------------
// PHASE 0: blockIdx.y = q in 0..15: c=q>>2, li=(q>>1)&1 (li=0 -> l=1, li=1 -> l=0), r=q&1
// PHASE 1: blockIdx.y = q in 0..7:  c=q>>1, r=q&1, l=1
template <int PHASE>
__global__ __launch_bounds__(256)
void het_all_kernel(const float* __restrict__ agg,
                    const float* __restrict__ convW, const float* __restrict__ convB,
                    const float* __restrict__ attnW1, const float* __restrict__ attnB1,
                    const float* __restrict__ attnW2,
                    const float* __restrict__ din_all,
                    float* __restrict__ hs_all, float* __restrict__ s_all) {
    constexpr int BM = 128, BK = 32, LDS_ = 136;
    extern __shared__ char smraw[];
    unsigned (*As)[LDS_]  = (unsigned(*)[LDS_])(smraw);
    unsigned (*Bs)[LDS_]  = (unsigned(*)[LDS_])(smraw + 32 * LDS_ * 4);
    unsigned (*HSs)[LDS_] = (unsigned(*)[LDS_])(smraw + 64 * LDS_ * 4);
    float* s_sm = (float*)(smraw + (64 + 128) * LDS_ * 4);

    const int q = blockIdx.y;
    int c, l, r;
    if (PHASE == 0) { c = q >> 2; l = ((q >> 1) & 1) ? 0 : 1; r = q & 1; }
    else            { c = q >> 1; l = 1; r = q & 1; }
    const int s = c >> 1;
    const int p = c * 2 + r;

    const float* A    = agg + (size_t)p * NH_;
    const float* W    = convW + (size_t)((s * 2 + l) * 2 + r) * HH_ * HH_;
    const float* bias = convB + (size_t)((s * 2 + l) * 2 + r) * HH_;
    const float* W1   = attnW1 + (size_t)(s * 2 + l) * HH_ * QQ_;
    const float* b1   = attnB1 + (size_t)(s * 2 + l) * QQ_;
    const float* w2   = attnW2 + (size_t)(s * 2 + l) * QQ_;
    const float* din  = din_all + p * NN_;
    float* hs_out = hs_all + (size_t)q * NH_;
    float* s_out  = s_all + (size_t)q * NN_;

    const int tid  = threadIdx.x;
    const int lane = tid & 31;
    const int warp = tid >> 5;
    const int grp  = lane >> 2;
    const int tig  = lane & 3;
    const int wm   = warp >> 1;
    const int wn   = warp & 1;
    const int mbase = wm * 32;
    const int block_m = blockIdx.x * BM;

    if (tid < 128) s_sm[tid] = 0.f;

    // ---------------- stage 1: conv GEMM (K=128, BN=128) ----------------
    float acc[2][8][4];
#pragma unroll
    for (int mf = 0; mf < 2; mf++)
#pragma unroll
        for (int nf = 0; nf < 8; nf++)
#pragma unroll
            for (int qq = 0; qq < 4; qq++) acc[mf][nf][qq] = 0.f;

    for (int k0 = 0; k0 < HH_; k0 += BK) {
        {
            int row = tid & 127;
            int f4b = tid >> 7;
            int gm = block_m + row;
            bool ok = (gm < NN_);
            const float* ap = A + (size_t)gm * HH_ + k0;
#pragma unroll
            for (int ii = 0; ii < 4; ii++) {
                int f4 = f4b + ii * 2;
                float4 v;
                if (ok) v = *(const float4*)(ap + f4 * 4);
                else { v.x = v.y = v.z = v.w = 0.f; }
                int kc = f4 * 4;
                As[kc + 0][row] = f2tf(v.x);
                As[kc + 1][row] = f2tf(v.y);
                As[kc + 2][row] = f2tf(v.z);
                As[kc + 3][row] = f2tf(v.w);
            }
        }
        {
            int f4 = tid & 31;
            int kb = tid >> 5;
#pragma unroll
            for (int ii = 0; ii < 4; ii++) {
                int k = kb + ii * 8;
                float4 v = *(const float4*)(W + (size_t)(k0 + k) * HH_ + f4 * 4);
                uint4 w;
                w.x = f2tf(v.x); w.y = f2tf(v.y); w.z = f2tf(v.z); w.w = f2tf(v.w);
                *(uint4*)&Bs[k][f4 * 4] = w;
            }
        }
        __syncthreads();
#pragma unroll
        for (int k8 = 0; k8 < BK; k8 += 8) {
            unsigned a[2][4];
#pragma unroll
            for (int mf = 0; mf < 2; mf++) {
                int r0 = mbase + mf * 16 + grp;
                a[mf][0] = As[k8 + tig][r0];
                a[mf][1] = As[k8 + tig][r0 + 8];
                a[mf][2] = As[k8 + tig + 4][r0];
                a[mf][3] = As[k8 + tig + 4][r0 + 8];
            }
#pragma unroll
            for (int nf = 0; nf < 8; nf++) {
                int n = wn * 64 + nf * 8 + grp;
                unsigned b0 = Bs[k8 + tig][n];
                unsigned b1 = Bs[k8 + tig + 4][n];
                mma8(acc[0][nf], a[0], b0, b1);
                mma8(acc[1][nf], a[1], b0, b1);
            }
        }
        __syncthreads();
    }

    // stage-1 epilogue: hs = acc*din + b; global write + transposed tf32 smem
#pragma unroll
    for (int mf = 0; mf < 2; mf++) {
        int rl0 = mbase + mf * 16 + grp;
#pragma unroll
        for (int nf = 0; nf < 8; nf++) {
            int col = wn * 64 + nf * 8 + tig * 2;
            float bc0 = bias[col], bc1 = bias[col + 1];
#pragma unroll
            for (int half = 0; half < 2; half++) {
                int rl = rl0 + half * 8;
                int rg = block_m + rl;
                float rs = (rg < NN_) ? din[rg] : 0.f;
                float v0 = acc[mf][nf][half * 2 + 0] * rs + bc0;
                float v1 = acc[mf][nf][half * 2 + 1] * rs + bc1;
                HSs[col][rl]     = f2tf(v0);
                HSs[col + 1][rl] = f2tf(v1);
                if (rg < NN_) {
                    float2 st; st.x = v0; st.y = v1;
                    *(float2*)(hs_out + (size_t)rg * HH_ + col) = st;
                }
            }
        }
    }
    __syncthreads();

    // ---------------- stage 2: t = tanh(hs@W1 + b1); s = t.w2 ----------------
    float acc2[2][4][4];
#pragma unroll
    for (int mf = 0; mf < 2; mf++)
#pragma unroll
        for (int nf = 0; nf < 4; nf++)
#pragma unroll
            for (int qq = 0; qq < 4; qq++) acc2[mf][nf][qq] = 0.f;

    for (int k0 = 0; k0 < HH_; k0 += BK) {
        {
            int f4 = tid & 15;
            int kb = tid >> 4;
#pragma unroll
            for (int ii = 0; ii < 2; ii++) {
                int k = kb + ii * 16;
                float4 v = *(const float4*)(W1 + (size_t)(k0 + k) * QQ_ + f4 * 4);
                uint4 w;
                w.x = f2tf(v.x); w.y = f2tf(v.y); w.z = f2tf(v.z); w.w = f2tf(v.w);
                *(uint4*)&Bs[k][f4 * 4] = w;
            }
        }
        __syncthreads();
#pragma unroll
        for (int k8 = 0; k8 < BK; k8 += 8) {
            unsigned a[2][4];
#pragma unroll
            for (int mf = 0; mf < 2; mf++) {
                int r0 = mbase + mf * 16 + grp;
                a[mf][0] = HSs[k0 + k8 + tig][r0];
                a[mf][1] = HSs[k0 + k8 + tig][r0 + 8];
                a[mf][2] = HSs[k0 + k8 + tig + 4][r0];
                a[mf][3] = HSs[k0 + k8 + tig + 4][r0 + 8];
            }
#pragma unroll
            for (int nf = 0; nf < 4; nf++) {
                int n = wn * 32 + nf * 8 + grp;
                unsigned b0 = Bs[k8 + tig][n];
                unsigned b1 = Bs[k8 + tig + 4][n];
                mma8(acc2[0][nf], a[0], b0, b1);
                mma8(acc2[1][nf], a[1], b0, b1);
            }
        }
        __syncthreads();
    }

    float part[2][2] = {{0.f, 0.f}, {0.f, 0.f}};
#pragma unroll
    for (int mf = 0; mf < 2; mf++)
#pragma unroll
        for (int nf = 0; nf < 4; nf++) {
            int col = wn * 32 + nf * 8 + tig * 2;
            float bc0 = b1[col], bc1 = b1[col + 1];
            float w20 = w2[col], w21 = w2[col + 1];
#pragma unroll
            for (int half = 0; half < 2; half++) {
                float v0 = tanhf(acc2[mf][nf][half * 2 + 0] + bc0);
                float v1 = tanhf(acc2[mf][nf][half * 2 + 1] + bc1);
                part[mf][half] += v0 * w20 + v1 * w21;
            }
        }
#pragma unroll
    for (int o = 1; o <= 2; o <<= 1) {
#pragma unroll
        for (int mf = 0; mf < 2; mf++)
#pragma unroll
            for (int half = 0; half < 2; half++)
                part[mf][half] += __shfl_xor_sync(0xffffffffu, part[mf][half], o);
    }
    if (tig == 0) {
#pragma unroll
        for (int mf = 0; mf < 2; mf++)
#pragma unroll
            for (int half = 0; half < 2; half++)
                atomicAdd(&s_sm[mbase + mf * 16 + grp + half * 8], part[mf][half]);
    }
    __syncthreads();
    if (tid < 128) {
        int rg = block_m + tid;
        if (rg < NN_) s_out[rg] = s_sm[tid];
    }
}

// ---------------- batched attention combine ---------------------------------
// PHASE 0: blockIdx.y = u in 0..7: c=u>>1, li=u&1; hs pair at q0=c*4+li*2;
//          out = (li==0 ? h1 : hA) + c*NH_
// PHASE 1: blockIdx.y = c in 0..3; hs pair at q0=c*2; out = h2 + c*NH_
template <int PHASE>
__global__ void combine_all_kernel(const float* __restrict__ hs_all,
                                   const float* __restrict__ s_all,
                                   float* __restrict__ h1b, float* __restrict__ hAb,
                                   float* __restrict__ h2b) {
    const int u = blockIdx.y;
    int q0, c;
    float* outb;
    if (PHASE == 0) {
        c = u >> 1;
        int li = u & 1;
        q0 = c * 4 + li * 2;
        outb = (li == 0 ? h1b : hAb);
    } else {
        c = u;
        q0 = c * 2;
        outb = h2b;
    }
    const float* hs0 = hs_all + (size_t)q0 * NH_;
    const float* hs1 = hs_all + (size_t)(q0 + 1) * NH_;
    const float* s0 = s_all + (size_t)q0 * NN_;
    const float* s1 = s_all + (size_t)(q0 + 1) * NN_;
    float* out = outb + (size_t)c * NH_;

    int warp = (blockIdx.x * blockDim.x + threadIdx.x) >> 5;
    int lane = threadIdx.x & 31;
    if (warp >= NN_) return;
    float sv0 = s0[warp], sv1 = s1[warp];
    float m = fmaxf(sv0, sv1);
    float e0 = expf(sv0 - m), e1 = expf(sv1 - m);
    float a0 = e0 / (e0 + e1), a1 = 1.f - a0;
    const float4* h0p = (const float4*)(hs0 + (size_t)warp * HH_);
    const float4* h1p = (const float4*)(hs1 + (size_t)warp * HH_);
    float4* op = (float4*)(out + (size_t)warp * HH_);
    float4 uu = h0p[lane];
    float4 vv = h1p[lane];
    float4 r;
    r.x = a0 * uu.x + a1 * vv.x;
    r.y = a0 * uu.y + a1 * vv.y;
    r.z = a0 * uu.z + a1 * vv.z;
    r.w = a0 * uu.w + a1 * vv.w;
    op[lane] = r;
}

// ---------------- host orchestration ----------------------------------------
extern "C" void kernel_launch(void* const* d_in, const int* in_sizes, int n_in,
                              void* d_out, int out_size) {
    const float* x_attr  = (const float*)d_in[0];
    const float* x_stru  = (const float*)d_in[1];
    const int*   e_attr  = (const int*)  d_in[2];
    const int*   e_stru  = (const int*)  d_in[3];
    const float* Wf      = (const float*)d_in[4];   // (2,H,F)
    const float* convW   = (const float*)d_in[5];   // (2,2,2,H,H)
    const float* convB   = (const float*)d_in[6];   // (2,2,2,H)
    const float* attnW1  = (const float*)d_in[7];   // (2,2,H,Q)
    const float* attnB1  = (const float*)d_in[8];   // (2,2,Q)
    const float* attnW2  = (const float*)d_in[9];   // (2,2,Q)
    const float* Wc      = (const float*)d_in[10];  // (2,H,3H)
    float* out = (float*)d_out;

    float *h0, *h1, *hA, *h2, *agg, *hs, *sb, *din, *dout;
    int *cnt_in, *cnt_out, *cursor, *off, *csr;
    cudaGetSymbolAddress((void**)&h0,  g_h0);
    cudaGetSymbolAddress((void**)&h1,  g_h1);
    cudaGetSymbolAddress((void**)&hA,  g_hA);
    cudaGetSymbolAddress((void**)&h2,  g_h2);
    cudaGetSymbolAddress((void**)&agg, g_agg);
    cudaGetSymbolAddress((void**)&hs,  g_hs);
    cudaGetSymbolAddress((void**)&sb,  g_s);
    cudaGetSymbolAddress((void**)&din,  g_din);
    cudaGetSymbolAddress((void**)&dout, g_dout);
    cudaGetSymbolAddress((void**)&cnt_in,  g_cnt_in);
    cudaGetSymbolAddress((void**)&cnt_out, g_cnt_out);
    cudaGetSymbolAddress((void**)&cursor,  g_cursor);
    cudaGetSymbolAddress((void**)&off, g_off);
    cudaGetSymbolAddress((void**)&csr, g_csr);

    const int TB = 256;
    const int gridM = (NN_ + 127) / 128;
    const int gridWarp = (NN_ + 7) / 8;
    const int HET_SMEM = (64 + 128) * 136 * 4 + 512;
    static int attrSet = 0;
    if (!attrSet) {
        cudaFuncSetAttribute(het_all_kernel<0>, cudaFuncAttributeMaxDynamicSharedMemorySize, HET_SMEM);
        cudaFuncSetAttribute(het_all_kernel<1>, cudaFuncAttributeMaxDynamicSharedMemorySize, HET_SMEM);
        attrSet = 1;
    }

    // 1) zero histogram counters
    zero_int_kernel<<<512, TB>>>(cnt_in, 8 * NN_);
    zero_int_kernel<<<512, TB>>>(cnt_out, 8 * NN_);

    // 2) h0 for all 4 runs (independent of CSR build)
    gemm_all_kernel<0><<<dim3(gridM, 4), TB>>>(x_attr, x_stru, Wf, Wc, h0, h1, h2, out);

    // 3) CSR build, all 8 pairs batched
    hist_all_kernel<<<dim3(256, 8), TB>>>(e_attr, e_stru, cnt_out, cnt_in);
    deg_all_kernel<<<(8 * NN_ + 255) / 256, TB>>>(cnt_in, cnt_out, din, dout);
    scan_all_kernel<<<8, 1024>>>(cnt_in, off, cursor);
    scatter_all_kernel<<<dim3(256, 8), TB>>>(e_attr, e_stru, cursor, csr);

    // 4) phase A: gather over h0 (8 pairs), het (16 combos), combine (8)
    gather_all_kernel<<<dim3(gridWarp, 8), TB>>>(h0, off, csr, dout, agg);
    het_all_kernel<0><<<dim3(gridM, 16), TB, HET_SMEM>>>(
        agg, convW, convB, attnW1, attnB1, attnW2, din, hs, sb);
    combine_all_kernel<0><<<dim3(gridWarp, 8), TB>>>(hs, sb, h1, hA, h2);

    // 5) phase B: gather over hA (8), het (8), combine (4)
    gather_all_kernel<<<dim3(gridWarp, 8), TB>>>(hA, off, csr, dout, agg);
    het_all_kernel<1><<<dim3(gridM, 8), TB, HET_SMEM>>>(
        agg, convW, convB, attnW1, attnB1, attnW2, din, hs, sb);
    combine_all_kernel<1><<<dim3(gridWarp, 4), TB>>>(hs, sb, h1, hA, h2);

    // 6) final: y = [h0|h1|h2] @ Wc^T for all 4 runs
    gemm_all_kernel<1><<<dim3(gridM, 4), TB>>>(x_attr, x_stru, Wf, Wc, h0, h1, h2, out);
}